// round 7
// baseline (speedup 1.0000x reference)
#include <cuda_runtime.h>
#include <cstdint>

#define BB 2
#define NN 256
#define FF 64
#define HH 64
#define KK 50
#define CC 256
#define NT 512

// ---------------- device scratch ----------------
__device__ float g_A [BB*NN*KK];
__device__ float g_Bb[BB*NN*KK];
__device__ float g_U [BB*NN*HH];
__device__ float g_Wp[BB*NN*HH];

typedef unsigned long long ull;

// ---------------- helpers ----------------
__device__ __forceinline__ uint32_t smem_u32(const void* p) {
    uint32_t a;
    asm("{ .reg .u64 t; cvta.to.shared.u64 t, %1; cvt.u32.u64 %0, t; }" : "=r"(a) : "l"(p));
    return a;
}
__device__ __forceinline__ float siluf(float a) { return a * __fdividef(1.f, 1.f + __expf(-a)); }
__device__ __forceinline__ float sigm(float a)  { return __fdividef(1.f, 1.f + __expf(-a)); }
__device__ __forceinline__ float ftanh(float x) {
    float e = __expf(-2.f * fabsf(x));
    return copysignf(__fdividef(1.f - e, 1.f + e), x);
}
__device__ __forceinline__ void fma2(ull& acc, ull a, ull b) {
    asm("fma.rn.f32x2 %0, %1, %2, %0;" : "+l"(acc) : "l"(a), "l"(b));
}
__device__ __forceinline__ ull bcast2(float w) {
    ull r; asm("mov.b64 %0, {%1, %1};" : "=l"(r) : "f"(w)); return r;
}
__device__ __forceinline__ ull pack2(float a, float b) {
    ull r; asm("mov.b64 %0, {%1, %2};" : "=l"(r) : "f"(a), "f"(b)); return r;
}
__device__ __forceinline__ void unpack2(ull v, float& x, float& y) {
    asm("mov.b64 {%0, %1}, %2;" : "=f"(x), "=f"(y) : "l"(v));
}
__device__ __forceinline__ void cp16(uint32_t dst, const void* src) {
    asm volatile("cp.async.cg.shared.global [%0], [%1], 16;" :: "r"(dst), "l"(src) : "memory");
}
#define CP_COMMIT() asm volatile("cp.async.commit_group;" ::: "memory")
#define CP_WAIT0()  asm volatile("cp.async.wait_group 0;" ::: "memory")

// block reduce of 4 floats over 16 warps. red >= 68 floats, 16B aligned.
template<int DO_MAX>
__device__ __forceinline__ float4 block_red4(float4 v, int tid, float* red) {
    #pragma unroll
    for (int o = 16; o > 0; o >>= 1) {
        float ax = __shfl_xor_sync(~0u, v.x, o), ay = __shfl_xor_sync(~0u, v.y, o);
        float az = __shfl_xor_sync(~0u, v.z, o), aw = __shfl_xor_sync(~0u, v.w, o);
        if (DO_MAX) { v.x = fmaxf(v.x, ax); v.y = fmaxf(v.y, ay); v.z = fmaxf(v.z, az); v.w = fmaxf(v.w, aw); }
        else        { v.x += ax; v.y += ay; v.z += az; v.w += aw; }
    }
    if ((tid & 31) == 0) ((float4*)red)[tid >> 5] = v;
    __syncthreads();
    if (tid < 32) {
        float4 r;
        if (tid < 16) r = ((float4*)red)[tid];
        else { float id = DO_MAX ? __int_as_float(0xff800000) : 0.f; r = make_float4(id, id, id, id); }
        #pragma unroll
        for (int o = 8; o > 0; o >>= 1) {
            float ax = __shfl_xor_sync(~0u, r.x, o), ay = __shfl_xor_sync(~0u, r.y, o);
            float az = __shfl_xor_sync(~0u, r.z, o), aw = __shfl_xor_sync(~0u, r.w, o);
            if (DO_MAX) { r.x = fmaxf(r.x, ax); r.y = fmaxf(r.y, ay); r.z = fmaxf(r.z, az); r.w = fmaxf(r.w, aw); }
            else        { r.x += ax; r.y += ay; r.z += az; r.w += aw; }
        }
        if (tid == 0) ((float4*)red)[16] = r;
    }
    __syncthreads();
    float4 out = ((float4*)red)[16];
    __syncthreads();
    return out;
}

// ---------------- K0: per-node precompute ----------------
__global__ void prenode_kernel(const float* __restrict__ h,
                               const float* __restrict__ W_in,
                               const float* __restrict__ W_o1) {
    __shared__ float hs[FF];
    int node = blockIdx.x, t = threadIdx.x;
    if (t < FF) hs[t] = h[node * FF + t];
    __syncthreads();
    if (t < KK) {
        float a = 0.f, bv = 0.f;
        #pragma unroll
        for (int f = 0; f < FF; f++) { float hv = hs[f]; a += hv * W_in[f*KK+t]; bv += hv * W_in[(FF+f)*KK+t]; }
        g_A[node*KK+t] = a; g_Bb[node*KK+t] = bv;
    } else if (t >= 64 && t < 128) {
        int c = t - 64;
        float u = 0.f, w = 0.f;
        #pragma unroll
        for (int f = 0; f < FF; f++) { float hv = hs[f]; u += hv * W_o1[f*HH+c]; w += hv * W_o1[(FF+f)*HH+c]; }
        g_U[node*HH+c] = u; g_Wp[node*HH+c] = w;
    }
}

// ---------------- smem layout (float offsets) ----------------
#define O_HE     0        // he[256 j][65] = 16640
#define O_ATT    16640    // 1024
#define O_XDN    17664    // 1024
#define O_CMX    18688    // 256
#define O_CMY    18944
#define O_CMZ    19200
#define O_CN     19456    // 256 (aliased as en_s during phase 1)
#define O_P1     19712
#define O_HCOMB  19776
#define O_N1     19840
#define O_HN     19904
#define O_HESUM  19968    // 256
#define O_HI     20224
#define O_WIB    20288
#define O_WON    20352
#define O_BO2    20416
#define O_BI     20480
#define O_MEAN   20544
#define O_BETA   20608
#define O_WS     20672    // 256
#define O_BSG    20928    // 8
#define O_XI     20936    // 4
#define O_RED    20940    // 68 (byte 83760, 16B aligned)
#define O_UNION  21008
// phase-1 view of union:
#define O_SARR   21008    // 256*50 = 12800
#define O_WO1K   33808    // 50*64 = 3200
#define O_WO2    37008    // 64*64 = 4096 -> 41104
// phase-4 view of union:
#define O_HET    21008    // [256 c][68] = 17408  (64 j + 16B hole after j=31)
#define O_WCH    38416    // 2 * 8192 = 16384 -> 54800
#define SMEM_FLOATS 54800
#define SMEM_BYTES  (SMEM_FLOATS*4)   // 219200

// ---------------- K1: fused per-(b,i) kernel, 512 threads ----------------
__global__ __launch_bounds__(NT, 1)
void sake_kernel(const float* __restrict__ h, const float* __restrict__ x,
                 const float* __restrict__ v,
                 const float* __restrict__ means, const float* __restrict__ betas,
                 const float* __restrict__ b_in,
                 const float* __restrict__ W_o1, const float* __restrict__ b_o1,
                 const float* __restrict__ W_o2, const float* __restrict__ b_o2,
                 const float* __restrict__ Ws,  const float* __restrict__ bs,
                 const float* __restrict__ log_gamma,
                 const float* __restrict__ Wx,
                 const float* __restrict__ Wp1, const float* __restrict__ bp1,
                 const float* __restrict__ Wp2, const float* __restrict__ bp2,
                 const float* __restrict__ Wn1, const float* __restrict__ bn1,
                 const float* __restrict__ Wn2, const float* __restrict__ bn2,
                 const float* __restrict__ Wv_mix,
                 const float* __restrict__ Wvel1, const float* __restrict__ bvel1,
                 const float* __restrict__ Wvel2,
                 float* __restrict__ outH, float* __restrict__ outX,
                 float* __restrict__ outV) {
    extern __shared__ float sm[];
    const int tid = threadIdx.x, wid = tid >> 5, lane = tid & 31;
    const int bid = blockIdx.x, b = bid >> 8, i = bid & 255, nodeI = bid;

    float* he    = sm + O_HE;     // [256 j][65]
    float* att_s = sm + O_ATT;
    float* xdn   = sm + O_XDN;
    float* en_s  = sm + O_CN;     // alias, phase-1 only
    float* he_e  = sm + O_HESUM;
    float* hi_s  = sm + O_HI;
    float* wib   = sm + O_WIB;
    float* won   = sm + O_WON;
    float* bo2_s = sm + O_BO2;
    float* bi_s  = sm + O_BI;
    float* mn_s  = sm + O_MEAN;
    float* bt_s  = sm + O_BETA;
    float* ws_s  = sm + O_WS;
    float* bsg   = sm + O_BSG;
    float* xi_s  = sm + O_XI;
    float* red   = sm + O_RED;
    float* sarr  = sm + O_SARR;
    float* wo1k  = sm + O_WO1K;
    float* wo2   = sm + O_WO2;
    float* heT   = sm + O_HET;

    const uint32_t smb = smem_u32(sm);

    // ---- preload ----
    if (tid < FF) {
        hi_s[tid]  = h[nodeI*FF+tid];
        wib[tid]   = g_Wp[nodeI*HH+tid] + b_o1[tid];
        won[tid]   = W_o1[178*HH+tid];
        bo2_s[tid] = b_o2[tid];
    }
    if (tid < KK) {
        bi_s[tid] = g_Bb[nodeI*KK+tid] + b_in[tid];
        mn_s[tid] = means[tid];
        bt_s[tid] = betas[tid];
    }
    if (tid < 256) ws_s[tid] = Ws[tid];
    if (tid < 4) {
        bsg[tid]   = bs[tid];
        bsg[4+tid] = __expf(log_gamma[tid]);
        if (tid < 3) xi_s[tid] = x[nodeI*3+tid];
    }
    for (int idx = tid; idx < NN*HH; idx += NT) {
        int j2 = idx >> 6, f = idx & 63;
        he[j2*65+f] = g_U[b*NN*HH + idx];
    }
    for (int idx = tid; idx < KK*HH; idx += NT) wo1k[idx] = W_o1[128*HH + idx];
    for (int idx = tid; idx < HH*HH; idx += NT) wo2[idx]  = W_o2[idx];
    __syncthreads();

    // ---- phase 0: geometry (thread pair (j, half)) ----
    const int j = tid >> 1, half = tid & 1, fb = half*32;
    float xjx = x[(b*NN+j)*3+0], xjy = x[(b*NN+j)*3+1], xjz = x[(b*NN+j)*3+2];
    float dx = xjx - xi_s[0], dy = xjy - xi_s[1], dz = xjz - xi_s[2];
    float d2 = fmaxf(dx*dx + dy*dy + dz*dz, 0.f);
    float normv = sqrtf(d2 + 1e-5f);
    float rinv  = __fdividef(1.f, normv + 1e-5f);
    if (half == 0) {
        *(float4*)&xdn[j*4] = make_float4(dx*rinv, dy*rinv, dz*rinv, normv);
        en_s[j] = __expf(-normv);
    }
    __syncthreads();

    // sarr[j][k] = rbf * hk (coalesced)
    for (int idx = tid; idx < NN*KK; idx += NT) {
        int j2 = idx / KK, k = idx - j2*KK;
        float aval = g_A[b*NN*KK + idx] + bi_s[k];
        float df = en_s[j2] - mn_s[k];
        sarr[idx] = __expf(-bt_s[k]*df*df) * aval;
    }
    __syncthreads();

    // ---- phase 1: edge model, pair-split over f ----
    {
        float accf[32];
        #pragma unroll
        for (int f = 0; f < 32; f++) accf[f] = he[j*65+fb+f] + wib[fb+f] + normv*won[fb+f];
        ull acc2[16];
        #pragma unroll
        for (int q = 0; q < 16; q++) acc2[q] = pack2(accf[2*q], accf[2*q+1]);

        #pragma unroll 2
        for (int k = 0; k < KK; k++) {
            ull s2 = bcast2(sarr[j*KK + k]);
            const ulonglong2* wr = (const ulonglong2*)&wo1k[k*64 + fb];
            #pragma unroll
            for (int q4 = 0; q4 < 8; q4++) {
                ulonglong2 wv = wr[q4];
                fma2(acc2[2*q4],   wv.x, s2);
                fma2(acc2[2*q4+1], wv.y, s2);
            }
        }
        #pragma unroll
        for (int q = 0; q < 16; q++) {
            float a0, a1; unpack2(acc2[q], a0, a1);
            he[j*65+fb+2*q]   = siluf(a0);
            he[j*65+fb+2*q+1] = siluf(a1);
        }
        __syncwarp();   // pair is in-warp: silu halves visible

        ull o2[16];
        const ulonglong2* bo = (const ulonglong2*)&bo2_s[fb];
        #pragma unroll
        for (int q = 0; q < 8; q++) { ulonglong2 bv = bo[q]; o2[2*q] = bv.x; o2[2*q+1] = bv.y; }
        #pragma unroll 8
        for (int fi = 0; fi < 64; fi++) {
            ull ab = bcast2(he[j*65+fi]);
            const ulonglong2* wr = (const ulonglong2*)&wo2[fi*64 + fb];
            #pragma unroll
            for (int q = 0; q < 8; q++) {
                ulonglong2 wv = wr[q];
                fma2(o2[2*q],   wv.x, ab);
                fma2(o2[2*q+1], wv.y, ab);
            }
        }
        __syncwarp();   // all reads of silu values done before overwrite
        #pragma unroll
        for (int q = 0; q < 16; q++) {
            float r0, r1; unpack2(o2[q], r0, r1);
            he[j*65+fb+2*q]   = r0;
            he[j*65+fb+2*q+1] = r1;
        }
    }
    __syncthreads();

    // ---- phase 2: attentions (pair combines via shfl) ----
    {
        float z0 = 0.f, z1 = 0.f, z2 = 0.f, z3 = 0.f;
        #pragma unroll 4
        for (int f = 0; f < 32; f++) {
            int ff = fb + ((f + (half << 4)) & 31);   // rotate to avoid pair bank clash
            float a = he[j*65+ff];
            z0 += a*ws_s[ff*4+0]; z1 += a*ws_s[ff*4+1];
            z2 += a*ws_s[ff*4+2]; z3 += a*ws_s[ff*4+3];
        }
        z0 += __shfl_xor_sync(~0u, z0, 1); z1 += __shfl_xor_sync(~0u, z1, 1);
        z2 += __shfl_xor_sync(~0u, z2, 1); z3 += __shfl_xor_sync(~0u, z3, 1);
        z0 += bsg[0]; z1 += bsg[1]; z2 += bsg[2]; z3 += bsg[3];
        z0 = (z0 > 0.f) ? z0 : 2.f*(__expf(0.5f*z0) - 1.f);
        z1 = (z1 > 0.f) ? z1 : 2.f*(__expf(0.5f*z1) - 1.f);
        z2 = (z2 > 0.f) ? z2 : 2.f*(__expf(0.5f*z2) - 1.f);
        z3 = (z3 > 0.f) ? z3 : 2.f*(__expf(0.5f*z3) - 1.f);
        float diag = (j == i) ? 1e5f : 0.f;
        float4 el = make_float4(-(normv+diag)*bsg[4], -(normv+diag)*bsg[5],
                                -(normv+diag)*bsg[6], -(normv+diag)*bsg[7]);
        float4 sl = make_float4(z0-diag, z1-diag, z2-diag, z3-diag);

        float4 m  = block_red4<1>(el, tid, red);   // duplicates safe for max
        float4 ee = make_float4(__expf(el.x-m.x), __expf(el.y-m.y), __expf(el.z-m.z), __expf(el.w-m.w));
        float4 eem = (half == 0) ? ee : make_float4(0,0,0,0);
        float4 s  = block_red4<0>(eem, tid, red);
        float4 eucl = make_float4(__fdividef(ee.x,s.x), __fdividef(ee.y,s.y),
                                  __fdividef(ee.z,s.z), __fdividef(ee.w,s.w));

        m  = block_red4<1>(sl, tid, red);
        ee = make_float4(__expf(sl.x-m.x), __expf(sl.y-m.y), __expf(sl.z-m.z), __expf(sl.w-m.w));
        eem = (half == 0) ? ee : make_float4(0,0,0,0);
        s  = block_red4<0>(eem, tid, red);
        float4 sem = make_float4(__fdividef(ee.x,s.x), __fdividef(ee.y,s.y),
                                 __fdividef(ee.z,s.z), __fdividef(ee.w,s.w));

        float4 q4 = make_float4(eucl.x*sem.x, eucl.y*sem.y, eucl.z*sem.z, eucl.w*sem.w);
        m  = block_red4<1>(q4, tid, red);
        ee = make_float4(__expf(q4.x-m.x), __expf(q4.y-m.y), __expf(q4.z-m.z), __expf(q4.w-m.w));
        eem = (half == 0) ? ee : make_float4(0,0,0,0);
        s  = block_red4<0>(eem, tid, red);
        if (half == 0) {
            att_s[j*4+0] = __fdividef(ee.x, s.x);
            att_s[j*4+1] = __fdividef(ee.y, s.y);
            att_s[j*4+2] = __fdividef(ee.z, s.z);
            att_s[j*4+3] = __fdividef(ee.w, s.w);
        }
    }
    __syncthreads();

    // ---- phase 3: h_e = sum_j he_att (pair splits j range) ----
    {
        const int c = tid >> 1, jh = tid & 1;
        const int fcol = c >> 2, hd = c & 3;
        float hs = 0.f;
        for (int jj = jh*128; jj < jh*128 + 128; jj++)
            hs += he[jj*65+fcol] * att_s[jj*4+hd];
        hs += __shfl_xor_sync(~0u, hs, 1);
        if (jh == 0) he_e[c] = hs;
    }

    // ---- phase 4: coeff = tanh(he_att @ Wx), reduced over j ----
    // 16 warps = 16 disjoint n-slices of 16 n. lane = jp(0..7)*4 + nq(0..3).
    // Thread tile: 8 j (4 packed pairs) x 4 n. Pass = 64 j; 4 passes.
    {
        const int jp = lane >> 2, nq = lane & 3;
        const int nb = wid*16 + nq*4;
        const int aofs = jp*8 + ((jp >= 4) ? 4 : 0);   // 16B hole after 128B
        const int cme = tid & 255, jhme = tid >> 8;
        const int fme = cme >> 2, hme = cme & 3;
        float cmxr[4] = {0,0,0,0}, cmyr[4] = {0,0,0,0}, cmzr[4] = {0,0,0,0};

        #define STAGE(chunk, buf) do { \
            uint32_t _dst = smb + (uint32_t)(O_WCH + (buf)*8192)*4u + (uint32_t)tid*16u; \
            const float* _src = Wx + (chunk)*8192 + tid*4; \
            cp16(_dst,           _src); \
            cp16(_dst +  8192u,  _src + 2048); \
            cp16(_dst + 16384u,  _src + 4096); \
            cp16(_dst + 24576u,  _src + 6144); \
            CP_COMMIT(); \
        } while(0)

        for (int pass = 0; pass < 4; pass++) {
            const int j0 = pass*64;
            __syncthreads();            // ring + heT of previous pass fully consumed
            STAGE(0, 0);
            // fill heT[c][jj'] with hole: jj<32 at jj, jj>=32 at jj+4
            {
                const int base = cme*68 + jhme*36;   // jh0 -> 0, jh1 -> 36
                #pragma unroll 8
                for (int jj = 0; jj < 32; jj++) {
                    int jn = j0 + jhme*32 + jj;
                    heT[base + jj] = he[jn*65 + fme] * att_s[jn*4 + hme];
                }
            }

            ull acc[4][4];
            #pragma unroll
            for (int n = 0; n < 4; n++)
                #pragma unroll
                for (int p = 0; p < 4; p++) acc[n][p] = 0ull;

            for (int t = 0; t < 8; t++) {
                CP_WAIT0();
                __syncthreads();        // buf t&1 + heT visible; compute(t-1) done
                if (t < 7) STAGE(t+1, (t+1)&1);

                const float* wb = sm + O_WCH + (t&1)*8192;
                const int cb = t*32;
                #pragma unroll 4
                for (int cc = 0; cc < 32; cc++) {
                    const ulonglong2* ap = (const ulonglong2*)&heT[(cb+cc)*68 + aofs];
                    ulonglong2 a01 = ap[0];   // j pairs {0,1},{2,3}
                    ulonglong2 a23 = ap[1];   // j pairs {4,5},{6,7}
                    float4 w4 = *(const float4*)&wb[cc*256 + nb];
                    ull wb0 = bcast2(w4.x), wb1 = bcast2(w4.y);
                    ull wb2 = bcast2(w4.z), wb3 = bcast2(w4.w);
                    fma2(acc[0][0], a01.x, wb0); fma2(acc[0][1], a01.y, wb0);
                    fma2(acc[0][2], a23.x, wb0); fma2(acc[0][3], a23.y, wb0);
                    fma2(acc[1][0], a01.x, wb1); fma2(acc[1][1], a01.y, wb1);
                    fma2(acc[1][2], a23.x, wb1); fma2(acc[1][3], a23.y, wb1);
                    fma2(acc[2][0], a01.x, wb2); fma2(acc[2][1], a01.y, wb2);
                    fma2(acc[2][2], a23.x, wb2); fma2(acc[2][3], a23.y, wb2);
                    fma2(acc[3][0], a01.x, wb3); fma2(acc[3][1], a01.y, wb3);
                    fma2(acc[3][2], a23.x, wb3); fma2(acc[3][3], a23.y, wb3);
                }
            }

            // epilogue: tanh + xd-weighted accumulate
            float4 xd[8];
            #pragma unroll
            for (int q = 0; q < 8; q++) xd[q] = *(const float4*)&xdn[(j0 + jp*8 + q)*4];
            #pragma unroll
            for (int n = 0; n < 4; n++) {
                #pragma unroll
                for (int p = 0; p < 4; p++) {
                    float c0, c1; unpack2(acc[n][p], c0, c1);
                    float t0 = ftanh(c0), t1 = ftanh(c1);
                    cmxr[n] += xd[2*p].x*t0 + xd[2*p+1].x*t1;
                    cmyr[n] += xd[2*p].y*t0 + xd[2*p+1].y*t1;
                    cmzr[n] += xd[2*p].z*t0 + xd[2*p+1].z*t1;
                }
            }
        }

        // reduce over jp (lane bits 2,3,4); lanes jp==0 store warp-exclusive n range
        #pragma unroll
        for (int n = 0; n < 4; n++) {
            #pragma unroll
            for (int o = 4; o <= 16; o <<= 1) {
                cmxr[n] += __shfl_xor_sync(~0u, cmxr[n], o);
                cmyr[n] += __shfl_xor_sync(~0u, cmyr[n], o);
                cmzr[n] += __shfl_xor_sync(~0u, cmzr[n], o);
            }
        }
        if (jp == 0) {
            #pragma unroll
            for (int n = 0; n < 4; n++) {
                sm[O_CMX + nb + n] = cmxr[n];
                sm[O_CMY + nb + n] = cmyr[n];
                sm[O_CMZ + nb + n] = cmzr[n];
            }
        }
    }
    __syncthreads();

    // ---- phase 5: comb_sum / comb_norm / delta_v ----
    float* cn    = sm + O_CN;
    float* p1_s  = sm + O_P1;
    float* hcomb = sm + O_HCOMB;
    float* n1_s  = sm + O_N1;
    float* hn_s  = sm + O_HN;
    const float invN = 1.f/256.f;
    float csx = 0.f, csy = 0.f, csz = 0.f, wv = 0.f;
    if (tid < 256) {
        csx = sm[O_CMX + tid]*invN;
        csy = sm[O_CMY + tid]*invN;
        csz = sm[O_CMZ + tid]*invN;
        cn[tid] = csx*csx + csy*csy + csz*csz;
        wv = Wv_mix[tid];
    }
    float4 dv4 = block_red4<0>(make_float4(wv*csx, wv*csy, wv*csz, 0.f), tid, red);

    // ---- phase 6: tail MLPs ----
    if (tid < 64) {
        float a = bp1[tid];
        for (int c = 0; c < CC; c++) a += cn[c] * Wp1[c*64+tid];
        p1_s[tid] = siluf(a);
    }
    __syncthreads();
    if (tid < 64) {
        float a = bp2[tid];
        for (int f = 0; f < 64; f++) a += p1_s[f] * Wp2[f*64+tid];
        hcomb[tid] = siluf(a);
    }
    __syncthreads();
    if (tid < 64) {
        float a = bn1[tid];
        for (int f = 0; f < 64; f++) a += hi_s[f]  * Wn1[f*64+tid];
        for (int c = 0; c < CC; c++) a += he_e[c]  * Wn1[(64+c)*64+tid];
        for (int f = 0; f < 64; f++) a += hcomb[f] * Wn1[(320+f)*64+tid];
        n1_s[tid] = siluf(a);
    }
    __syncthreads();
    if (tid < 64) {
        float a = bn2[tid];
        for (int f = 0; f < 64; f++) a += n1_s[f] * Wn2[f*64+tid];
        float hv = hi_s[tid] + siluf(a);
        hn_s[tid] = hv;
        outH[nodeI*64+tid] = hv;
    }
    __syncthreads();
    float vl = 0.f;
    if (tid < 64) {
        float a = bvel1[tid];
        for (int f = 0; f < 64; f++) a += hn_s[f] * Wvel1[f*64+tid];
        vl = siluf(a) * Wvel2[tid];
    }
    float4 vs = block_red4<0>(make_float4(vl, 0.f, 0.f, 0.f), tid, red);
    if (tid == 0) {
        float scale = 2.f * sigm(vs.x);
        float dvv[3] = {dv4.x, dv4.y, dv4.z};
        #pragma unroll
        for (int t = 0; t < 3; t++) {
            float vn = dvv[t] + scale * v[nodeI*3+t];
            outV[nodeI*3+t] = vn;
            outX[nodeI*3+t] = x[nodeI*3+t] + vn;
        }
    }
}

// ---------------- launch ----------------
extern "C" void kernel_launch(void* const* d_in, const int* in_sizes, int n_in,
                              void* d_out, int out_size) {
    const float* h      = (const float*)d_in[0];
    const float* x      = (const float*)d_in[1];
    const float* v      = (const float*)d_in[2];
    const float* means  = (const float*)d_in[3];
    const float* betas  = (const float*)d_in[4];
    const float* W_in   = (const float*)d_in[5];
    const float* b_in   = (const float*)d_in[6];
    const float* W_o1   = (const float*)d_in[7];
    const float* b_o1   = (const float*)d_in[8];
    const float* W_o2   = (const float*)d_in[9];
    const float* b_o2   = (const float*)d_in[10];
    const float* Ws     = (const float*)d_in[11];
    const float* bs     = (const float*)d_in[12];
    const float* lgam   = (const float*)d_in[13];
    const float* Wx     = (const float*)d_in[14];
    const float* Wp1    = (const float*)d_in[15];
    const float* bp1    = (const float*)d_in[16];
    const float* Wp2    = (const float*)d_in[17];
    const float* bp2    = (const float*)d_in[18];
    const float* Wn1    = (const float*)d_in[19];
    const float* bn1    = (const float*)d_in[20];
    const float* Wn2    = (const float*)d_in[21];
    const float* bn2    = (const float*)d_in[22];
    const float* Wv_mix = (const float*)d_in[23];
    const float* Wvel1  = (const float*)d_in[24];
    const float* bvel1  = (const float*)d_in[25];
    const float* Wvel2  = (const float*)d_in[26];

    float* out  = (float*)d_out;
    float* outH = out;
    float* outX = out + BB*NN*FF;
    float* outV = outX + BB*NN*3;

    cudaFuncSetAttribute(sake_kernel, cudaFuncAttributeMaxDynamicSharedMemorySize, SMEM_BYTES);

    prenode_kernel<<<BB*NN, 128>>>(h, W_in, W_o1);
    sake_kernel<<<BB*NN, NT, SMEM_BYTES>>>(
        h, x, v, means, betas, b_in, W_o1, b_o1, W_o2, b_o2,
        Ws, bs, lgam, Wx, Wp1, bp1, Wp2, bp2,
        Wn1, bn1, Wn2, bn2, Wv_mix, Wvel1, bvel1, Wvel2,
        outH, outX, outV);
}